// round 10
// baseline (speedup 1.0000x reference)
#include <cuda_runtime.h>
#include <cuda_bf16.h>
#include <stdint.h>

// ---------------------------------------------------------------------------
// AdaptiveLogits on GB300 — mma.sync (HMMA) bf16 hi/lo-split GEMMs.
// tcgen05 unavailable (harness ptxas targets sm_103, no 'a').
//   out = [ head (B x 2002) | logits0 (B x 18000) | logits1 (B x 80001) ]
// fp32 = hi + lo (bf16 each); C = Ahi*Bhi + Ahi*Blo + Alo*Bhi (err ~2^-16).
// R10: grid order m-fastest (B-weight L2/DRAM reuse), merged conv launch,
// GEMM launch order puts tail-1 logits at index 5 for the ncu window.
// ---------------------------------------------------------------------------

#define C0 2000
#define C1 20000
#define C2 100001
#define HID 1024
#define HID_RF 256
#define BATCH_MAX 4096

#define N_HEAD (C0 + 2)   /* 2002  */
#define N_T0   (C1 - C0)  /* 18000 */
#define N_T1   (C2 - C1)  /* 80001 */

typedef __nv_bfloat16 bf16;

// ---- device scratch (static; allocation forbidden) ------------------------
__device__ int g_cnt0;
__device__ int g_cnt1;
__device__ int g_rows0[BATCH_MAX];
__device__ int g_rows1[BATCH_MAX];

__device__ __align__(16) bf16 g_hid_hi[(size_t)BATCH_MAX * HID];
__device__ __align__(16) bf16 g_hid_lo[(size_t)BATCH_MAX * HID];
__device__ __align__(16) bf16 g_h0_hi[(size_t)BATCH_MAX * HID];
__device__ __align__(16) bf16 g_h0_lo[(size_t)BATCH_MAX * HID];
__device__ __align__(16) bf16 g_h1_hi[(size_t)BATCH_MAX * HID_RF];
__device__ __align__(16) bf16 g_h1_lo[(size_t)BATCH_MAX * HID_RF];
__device__ __align__(16) bf16 g_wh_hi[(size_t)N_HEAD * HID];
__device__ __align__(16) bf16 g_wh_lo[(size_t)N_HEAD * HID];
__device__ __align__(16) bf16 g_ct0_hi[(size_t)N_T0 * HID];
__device__ __align__(16) bf16 g_ct0_lo[(size_t)N_T0 * HID];
__device__ __align__(16) bf16 g_d1_hi[(size_t)N_T1 * HID_RF];
__device__ __align__(16) bf16 g_d1_lo[(size_t)N_T1 * HID_RF];
__device__ __align__(16) bf16 g_dn0_hi[(size_t)HID * HID];
__device__ __align__(16) bf16 g_dn0_lo[(size_t)HID * HID];
__device__ __align__(16) bf16 g_dn1_hi[(size_t)HID_RF * HID];
__device__ __align__(16) bf16 g_dn1_lo[(size_t)HID_RF * HID];

// ---- helpers ---------------------------------------------------------------
__device__ __forceinline__ uint32_t smem_u32(const void* p) {
    uint32_t a;
    asm("{ .reg .u64 t; cvta.to.shared.u64 t, %1; cvt.u32.u64 %0, t; }"
        : "=r"(a) : "l"(p));
    return a;
}

#define LDM4(r, a) \
    asm volatile("ldmatrix.sync.aligned.m8n8.x4.shared.b16 {%0,%1,%2,%3}, [%4];" \
        : "=r"((r)[0]), "=r"((r)[1]), "=r"((r)[2]), "=r"((r)[3]) : "r"(a))

#define MMA16816(d, a, b0v, b1v) \
    asm volatile("mma.sync.aligned.m16n8k16.row.col.f32.bf16.bf16.f32 " \
        "{%0,%1,%2,%3}, {%4,%5,%6,%7}, {%8,%9}, {%0,%1,%2,%3};" \
        : "+f"((d)[0]), "+f"((d)[1]), "+f"((d)[2]), "+f"((d)[3]) \
        : "r"((a)[0]), "r"((a)[1]), "r"((a)[2]), "r"((a)[3]), \
          "r"(b0v), "r"(b1v))

// ---- bucket classification -------------------------------------------------
__global__ void init_counts_k() { g_cnt0 = 0; g_cnt1 = 0; }

__global__ void classify_k(const int* __restrict__ targets, int B) {
    int b = blockIdx.x * blockDim.x + threadIdx.x;
    if (b >= B) return;
    int t = targets[b];
    if (t >= C0 && t < C1) g_rows0[atomicAdd(&g_cnt0, 1)] = b;
    else if (t >= C1)      g_rows1[atomicAdd(&g_cnt1, 1)] = b;
}

// ---- fp32 -> bf16 hi/lo split: all 7 regions in ONE launch ------------------
struct ConvSeg { const float* src; bf16* hi; bf16* lo; long long beg; };
struct ConvTab { ConvSeg s[7]; long long total; };

__global__ void conv_all_k(ConvTab t) {
    long long i = (long long)blockIdx.x * blockDim.x + threadIdx.x;
    if (i >= t.total) return;
    int j = 0;
#pragma unroll
    for (int k = 1; k < 7; ++k) if (i >= t.s[k].beg) j = k;
    const long long li = i - t.s[j].beg;
    float4 v = reinterpret_cast<const float4*>(t.s[j].src)[li];
    bf16 hx = __float2bfloat16(v.x), hy = __float2bfloat16(v.y);
    bf16 hz = __float2bfloat16(v.z), hw = __float2bfloat16(v.w);
    bf16 lx = __float2bfloat16(v.x - __bfloat162float(hx));
    bf16 ly = __float2bfloat16(v.y - __bfloat162float(hy));
    bf16 lz = __float2bfloat16(v.z - __bfloat162float(hz));
    bf16 lw = __float2bfloat16(v.w - __bfloat162float(hw));
    __nv_bfloat162* H = reinterpret_cast<__nv_bfloat162*>(t.s[j].hi);
    __nv_bfloat162* L = reinterpret_cast<__nv_bfloat162*>(t.s[j].lo);
    H[2 * li]     = __halves2bfloat162(hx, hy);
    H[2 * li + 1] = __halves2bfloat162(hz, hw);
    L[2 * li]     = __halves2bfloat162(lx, ly);
    L[2 * li + 1] = __halves2bfloat162(lz, lw);
}

// ---- zero-fill inactive rows -----------------------------------------------
__global__ void zero0_k(const int* __restrict__ targets, float* __restrict__ out0) {
    int b = blockIdx.x;
    int t = targets[b];
    if (t >= C0 && t < C1) return;
    float4* p = reinterpret_cast<float4*>(out0 + (long long)b * N_T0);
    const float4 z = make_float4(0.f, 0.f, 0.f, 0.f);
    for (int i = threadIdx.x; i < N_T0 / 4; i += blockDim.x) p[i] = z;
}

__global__ void zero1_k(const int* __restrict__ targets, float* __restrict__ out1) {
    int b = blockIdx.x;
    int t = targets[b];
    if (t >= C1) return;
    long long base = (long long)b * N_T1;
    float* p = out1 + base;
    int lead = (int)((4 - (base & 3)) & 3);
    int nv = (N_T1 - lead) / 4;
    int tail_start = lead + nv * 4;
    if (threadIdx.x < (unsigned)lead) p[threadIdx.x] = 0.f;
    float4* pv = reinterpret_cast<float4*>(p + lead);
    const float4 z = make_float4(0.f, 0.f, 0.f, 0.f);
    for (int i = threadIdx.x; i < nv; i += blockDim.x) pv[i] = z;
    for (int i = tail_start + (int)threadIdx.x; i < N_T1; i += blockDim.x) p[i] = 0.f;
}

// ---- mma.sync bf16-split GEMM ----------------------------------------------
// C[i][n] = sum_k A[rowA(i)][k] * B[n][k]  via Ahi*Bhi + Ahi*Blo + Alo*Bhi.
// Tile BM=128 x BN=64, BK=32 bf16/stage, 256 thr (8 warps 4x2, warp 32x32).
// Grid: x = M blocks (FAST — consecutive CTAs share the same B tile, so
// B weights stream from DRAM ~once and are reused via L2), y = N blocks.
#define BM 128
#define BN 64
#define LDT 40   /* padded smem row stride, bf16 units */

__global__ __launch_bounds__(256)
void gemm_mma(const bf16* __restrict__ Ahi, const bf16* __restrict__ Alo, int lda,
              const int* __restrict__ rowsA, const int* __restrict__ pcnt, int Mmax,
              const bf16* __restrict__ Bhi, const bf16* __restrict__ Blo,
              int ldb, int N, int K,
              float* __restrict__ C, long long ldc, const int* __restrict__ rowsC,
              bf16* __restrict__ outHi, bf16* __restrict__ outLo) {
    const int Meff = pcnt ? *pcnt : Mmax;
    const int m0 = blockIdx.x * BM;      // M on x: fastest-varying
    if (m0 >= Meff) return;
    const int n0 = blockIdx.y * BN;      // N on y: B tile shared by x-run

    __shared__ __align__(16) bf16 sAh[BM * LDT];
    __shared__ __align__(16) bf16 sAl[BM * LDT];
    __shared__ __align__(16) bf16 sBh[BN * LDT];
    __shared__ __align__(16) bf16 sBl[BN * LDT];

    const int tid = threadIdx.x;
    const int lid = tid & 31;
    const int wid = tid >> 5;

    // ---- staging mapping ----
    const int srow = tid >> 1, sseg = tid & 1;       // A: row, 32B half
    int ai = m0 + srow;
    long long arow = 0;
    if (ai < Meff) arow = rowsA ? rowsA[ai] : ai;
    const bf16* aH = Ahi + arow * lda + sseg * 16;
    const bf16* aL = Alo + arow * lda + sseg * 16;
    const int brow = tid >> 2, bseg = tid & 3;       // B: row, 16B quarter
    int bn = n0 + brow; if (bn >= N) bn = 0;
    const bf16* bH = Bhi + (long long)bn * ldb + bseg * 8;
    const bf16* bL = Blo + (long long)bn * ldb + bseg * 8;

    const int sa_off = srow * LDT + sseg * 16;
    const int sb_off = brow * LDT + bseg * 8;

    // ---- compute mapping ----
    const int wm = wid >> 1;          // 0..3  (m warp, 32 rows)
    const int wn = wid & 1;           // 0..1  (n warp, 32 cols)
    const int lrow = lid & 15;
    const int lsel = lid >> 4;

    const uint32_t aHb = smem_u32(sAh), aLb = smem_u32(sAl);
    const uint32_t bHb = smem_u32(sBh), bLb = smem_u32(sBl);
    const uint32_t a_lane = (uint32_t)((wm * 32 + lrow) * LDT + lsel * 8) * 2;
    const uint32_t b_lane = (uint32_t)((wn * 32 + lrow) * LDT + lsel * 8) * 2;

    float acc[2][4][4];
#pragma unroll
    for (int mi = 0; mi < 2; ++mi)
#pragma unroll
        for (int nj = 0; nj < 4; ++nj)
#pragma unroll
            for (int e = 0; e < 4; ++e) acc[mi][nj][e] = 0.f;

    // prefetch stage 0
    uint4 pah0 = *reinterpret_cast<const uint4*>(aH);
    uint4 pah1 = *reinterpret_cast<const uint4*>(aH + 8);
    uint4 pal0 = *reinterpret_cast<const uint4*>(aL);
    uint4 pal1 = *reinterpret_cast<const uint4*>(aL + 8);
    uint4 pbh  = *reinterpret_cast<const uint4*>(bH);
    uint4 pbl  = *reinterpret_cast<const uint4*>(bL);

    const int niter = K >> 5;  // BK=32
    for (int it = 0; it < niter; ++it) {
        if (it) __syncthreads();
        *reinterpret_cast<uint4*>(sAh + sa_off)     = pah0;
        *reinterpret_cast<uint4*>(sAh + sa_off + 8) = pah1;
        *reinterpret_cast<uint4*>(sAl + sa_off)     = pal0;
        *reinterpret_cast<uint4*>(sAl + sa_off + 8) = pal1;
        *reinterpret_cast<uint4*>(sBh + sb_off)     = pbh;
        *reinterpret_cast<uint4*>(sBl + sb_off)     = pbl;
        __syncthreads();

        const int kn = (it + 1) << 5;
        if (kn < K) {  // prefetch next stage (overlaps compute)
            pah0 = *reinterpret_cast<const uint4*>(aH + kn);
            pah1 = *reinterpret_cast<const uint4*>(aH + kn + 8);
            pal0 = *reinterpret_cast<const uint4*>(aL + kn);
            pal1 = *reinterpret_cast<const uint4*>(aL + kn + 8);
            pbh  = *reinterpret_cast<const uint4*>(bH + kn);
            pbl  = *reinterpret_cast<const uint4*>(bL + kn);
        }

#pragma unroll
        for (int kc = 0; kc < 32; kc += 16) {
            uint32_t ah[8], al[8], bh[8], bl[8];
            const uint32_t kb = (uint32_t)kc * 2;
            LDM4(ah + 0, aHb + a_lane + kb);
            LDM4(ah + 4, aHb + a_lane + kb + (uint32_t)(16 * LDT * 2));
            LDM4(al + 0, aLb + a_lane + kb);
            LDM4(al + 4, aLb + a_lane + kb + (uint32_t)(16 * LDT * 2));
            LDM4(bh + 0, bHb + b_lane + kb);
            LDM4(bh + 4, bHb + b_lane + kb + (uint32_t)(16 * LDT * 2));
            LDM4(bl + 0, bLb + b_lane + kb);
            LDM4(bl + 4, bLb + b_lane + kb + (uint32_t)(16 * LDT * 2));
#pragma unroll
            for (int mi = 0; mi < 2; ++mi) {
#pragma unroll
                for (int nj = 0; nj < 4; ++nj) {
                    const int g = (nj >> 1) * 4, s = nj & 1;
                    MMA16816(acc[mi][nj], ah + mi * 4, bh[g + s], bh[g + 2 + s]);
                    MMA16816(acc[mi][nj], ah + mi * 4, bl[g + s], bl[g + 2 + s]);
                    MMA16816(acc[mi][nj], al + mi * 4, bh[g + s], bh[g + 2 + s]);
                }
            }
        }
    }

    // ---- epilogue ----
    const int col0 = n0 + wn * 32 + (lid & 3) * 2;
#pragma unroll
    for (int mi = 0; mi < 2; ++mi) {
        const int i0 = m0 + wm * 32 + mi * 16 + (lid >> 2);
        const int i1 = i0 + 8;
#pragma unroll
        for (int half = 0; half < 2; ++half) {
            const int i = half ? i1 : i0;
            if (i >= Meff) continue;
            if (outHi) {
                long long base = (long long)i * ldc;
#pragma unroll
                for (int nj = 0; nj < 4; ++nj) {
                    int col = col0 + nj * 8;
#pragma unroll
                    for (int e = 0; e < 2; ++e) {
                        if (col + e < N) {
                            float v = acc[mi][nj][half * 2 + e];
                            bf16 h = __float2bfloat16(v);
                            outHi[base + col + e] = h;
                            outLo[base + col + e] =
                                __float2bfloat16(v - __bfloat162float(h));
                        }
                    }
                }
            } else {
                long long orow = rowsC ? (long long)rowsC[i] : (long long)i;
                float* Crow = C + orow * ldc;
#pragma unroll
                for (int nj = 0; nj < 4; ++nj) {
                    int col = col0 + nj * 8;
                    if (col + 1 < N) {
                        Crow[col]     = acc[mi][nj][half * 2 + 0];
                        Crow[col + 1] = acc[mi][nj][half * 2 + 1];
                    } else {
                        if (col < N) Crow[col] = acc[mi][nj][half * 2 + 0];
                    }
                }
            }
        }
    }
}

// ---------------------------------------------------------------------------
extern "C" void kernel_launch(void* const* d_in, const int* in_sizes, int n_in,
                              void* d_out, int out_size) {
    const float* hidden  = (const float*)d_in[0];  // (B, 1024)
    const int*   targets = (const int*)  d_in[1];  // (B,)
    const float* cand    = (const float*)d_in[2];  // (100001, 1024)
    const float* tailv   = (const float*)d_in[3];  // (2, 1024)
    const float* down0   = (const float*)d_in[4];  // (1024, 1024)
    const float* down1   = (const float*)d_in[5];  // (256, 1024)
    const float* dec1    = (const float*)d_in[6];  // (80001, 256)
    float* out = (float*)d_out;

    const int B = in_sizes[1];  // 4096

    float* outH = out;
    float* out0 = outH + (size_t)B * N_HEAD;
    float* out1 = out0 + (size_t)B * N_T0;

    int *p_cnt0, *p_cnt1, *p_rows0, *p_rows1;
    bf16 *hid_hi, *hid_lo, *h0_hi, *h0_lo, *h1_hi, *h1_lo;
    bf16 *wh_hi, *wh_lo, *ct0_hi, *ct0_lo, *d1_hi, *d1_lo;
    bf16 *dn0_hi, *dn0_lo, *dn1_hi, *dn1_lo;
#define SYM(p, s) cudaGetSymbolAddress((void**)&(p), s)
    SYM(p_cnt0, g_cnt0);   SYM(p_cnt1, g_cnt1);
    SYM(p_rows0, g_rows0); SYM(p_rows1, g_rows1);
    SYM(hid_hi, g_hid_hi); SYM(hid_lo, g_hid_lo);
    SYM(h0_hi, g_h0_hi);   SYM(h0_lo, g_h0_lo);
    SYM(h1_hi, g_h1_hi);   SYM(h1_lo, g_h1_lo);
    SYM(wh_hi, g_wh_hi);   SYM(wh_lo, g_wh_lo);
    SYM(ct0_hi, g_ct0_hi); SYM(ct0_lo, g_ct0_lo);
    SYM(d1_hi, g_d1_hi);   SYM(d1_lo, g_d1_lo);
    SYM(dn0_hi, g_dn0_hi); SYM(dn0_lo, g_dn0_lo);
    SYM(dn1_hi, g_dn1_hi); SYM(dn1_lo, g_dn1_lo);
#undef SYM

    const int mb = (B + BM - 1) / BM;  // 32

    // launch 0-1: classify rows
    init_counts_k<<<1, 1>>>();
    classify_k<<<(B + 255) / 256, 256>>>(targets, B);

    // launch 2: all fp32 -> bf16 hi/lo conversions in one kernel
    {
        ConvTab t;
        long long off = 0;
        auto seg = [&](int j, const float* s, bf16* h, bf16* l, long long n) {
            t.s[j].src = s; t.s[j].hi = h; t.s[j].lo = l; t.s[j].beg = off;
            off += n / 4;
        };
        seg(0, cand, wh_hi, wh_lo, (long long)C0 * HID);
        seg(1, tailv, wh_hi + (size_t)C0 * HID, wh_lo + (size_t)C0 * HID, 2LL * HID);
        seg(2, cand + (size_t)C0 * HID, ct0_hi, ct0_lo, (long long)N_T0 * HID);
        seg(3, dec1, d1_hi, d1_lo, (long long)N_T1 * HID_RF);
        seg(4, down0, dn0_hi, dn0_lo, (long long)HID * HID);
        seg(5, down1, dn1_hi, dn1_lo, (long long)HID_RF * HID);
        seg(6, hidden, hid_hi, hid_lo, (long long)B * HID);
        t.total = off;
        int blocks = (int)((off + 255) / 256);
        conv_all_k<<<blocks, 256>>>(t);
    }

    // launch 3: tail0 down-proj (gather rows0) -> h0 hi/lo
    gemm_mma<<<dim3(mb, HID / BN), 256>>>(
        hid_hi, hid_lo, HID, p_rows0, p_cnt0, B,
        dn0_hi, dn0_lo, HID, HID, HID,
        nullptr, (long long)HID, nullptr, h0_hi, h0_lo);

    // launch 4: tail1 down-proj (gather rows1) -> h1 hi/lo
    gemm_mma<<<dim3(mb, HID_RF / BN), 256>>>(
        hid_hi, hid_lo, HID, p_rows1, p_cnt1, B,
        dn1_hi, dn1_lo, HID, HID_RF, HID,
        nullptr, (long long)HID_RF, nullptr, h1_hi, h1_lo);

    // launch 5 (ncu -s 5 -c 1 window): tail1 logits — the dominant GEMM
    gemm_mma<<<dim3(mb, (N_T1 + BN - 1) / BN), 256>>>(
        h1_hi, h1_lo, HID_RF, nullptr, p_cnt1, B,
        d1_hi, d1_lo, HID_RF, N_T1, HID_RF,
        out1, (long long)N_T1, p_rows1, nullptr, nullptr);

    // launch 6: tail0 logits
    gemm_mma<<<dim3(mb, (N_T0 + BN - 1) / BN), 256>>>(
        h0_hi, h0_lo, HID, nullptr, p_cnt0, B,
        ct0_hi, ct0_lo, HID, N_T0, HID,
        out0, (long long)N_T0, p_rows0, nullptr, nullptr);

    // launch 7: head
    gemm_mma<<<dim3(mb, (N_HEAD + BN - 1) / BN), 256>>>(
        hid_hi, hid_lo, HID, nullptr, nullptr, B,
        wh_hi, wh_lo, HID, N_HEAD, HID,
        outH, (long long)N_HEAD, nullptr, nullptr, nullptr);

    // launches 8-9: zero inactive rows exactly once
    zero0_k<<<B, 256>>>(targets, out0);
    zero1_k<<<B, 256>>>(targets, out1);

    (void)n_in; (void)out_size;
}